// round 11
// baseline (speedup 1.0000x reference)
#include <cuda_runtime.h>
#include <cstdint>

// Problem constants (from reference):
//   x: [B=64, E=2048] int32, values in [1, 2047]
//   Y: [J=2048, E=2048, B=64] float32
//   Y[j,e,b] = ((2*x[b,j]+1) >> min(E-1-e, 31)) & 1
// v = 2*x+1 <= 4095 < 2^12  =>  bit is 0 for all e < E-13 = 2035.
// Only the last 13 e-columns per j are nonzero (~0.64% of 1.07 GB).
//
// History:
//   R3 flat 2x/thr (split):    145.8us, DRAM 89.3%
//   R4 flat 4x/thr (split):    145.5us, DRAM 89.2%  <- prior best
//   R7 persistent 1-wave:      174.1us, DRAM 75.0%  (regression)
//   R9/R10 confirms:           145.5-145.6us        (stable)
// This round: CONTIGUOUS 4 float4s per thread (16 consecutive floats,
// one 8KB span per warp) instead of 4 stores 256MB apart -> one DRAM
// write stream per warp (row-buffer locality), and the (j,e) branch +
// shift computed once per thread instead of 4x.

constexpr int E_DIM = 2048;
constexpr unsigned NONZERO_E_START = E_DIM - 13;  // 2035

// Total float4 elements: J * E * B / 4 = 2048 * 2048 * 16 = 67,108,864
constexpr unsigned TOTAL_F4 = (unsigned)E_DIM * (unsigned)E_DIM * 16u;

// Streaming store: evict-first, output is dead-on-write (no reuse).
__device__ __forceinline__ void stg_cs_f4(float4* p, float4 v) {
    asm volatile("st.global.cs.v4.f32 [%0], {%1, %2, %3, %4};"
                 :: "l"(p), "f"(v.x), "f"(v.y), "f"(v.z), "f"(v.w)
                 : "memory");
}

__global__ void embedding_bits_kernel(const int* __restrict__ x,
                                      float4* __restrict__ out) {
    // Thread t owns float4 indices [4t, 4t+3] = 16 consecutive floats.
    // Since 4t is 4-aligned and each (j,e) pair owns a 16-float4-aligned
    // group, all 4 float4s share the same (j, e).
    unsigned t    = blockIdx.x * blockDim.x + threadIdx.x;
    unsigned idx4 = t << 2;               // first float4 index
    unsigned pair = idx4 >> 4;            // j * E + e
    unsigned e    = pair & (E_DIM - 1);   // E is a power of two

    float4 r0 = make_float4(0.f, 0.f, 0.f, 0.f);
    float4 r1 = r0, r2 = r0, r3 = r0;

    if (e >= NONZERO_E_START) {           // ~0.64% of threads
        unsigned j = pair >> 11;          // pair / E
        unsigned b = (idx4 & 15u) << 2;   // first of 16 batch lanes
        int shift = (E_DIM - 1) - (int)e; // in [0, 12]
        float v[16];
        #pragma unroll
        for (int i = 0; i < 16; i++) {
            int val = 2 * __ldg(&x[(b + i) * E_DIM + j]) + 1;
            v[i] = (float)((val >> shift) & 1);
        }
        r0 = make_float4(v[0],  v[1],  v[2],  v[3]);
        r1 = make_float4(v[4],  v[5],  v[6],  v[7]);
        r2 = make_float4(v[8],  v[9],  v[10], v[11]);
        r3 = make_float4(v[12], v[13], v[14], v[15]);
    }

    // Four contiguous STG.128.CS: warp covers one 8KB contiguous span.
    float4* p = &out[idx4];
    stg_cs_f4(p + 0, r0);
    stg_cs_f4(p + 1, r1);
    stg_cs_f4(p + 2, r2);
    stg_cs_f4(p + 3, r3);
}

extern "C" void kernel_launch(void* const* d_in, const int* in_sizes, int n_in,
                              void* d_out, int out_size) {
    const int* x = (const int*)d_in[0];
    float4* out = (float4*)d_out;

    constexpr int THREADS = 256;
    constexpr unsigned BLOCKS = (TOTAL_F4 / 4) / THREADS;  // 65,536 (exact)
    embedding_bits_kernel<<<BLOCKS, THREADS>>>(x, out);
}

// round 12
// speedup vs baseline: 1.6751x; 1.6751x over previous
#include <cuda_runtime.h>
#include <cstdint>

// Problem constants (from reference):
//   x: [B=64, E=2048] int32, values in [1, 2047]
//   Y: [J=2048, E=2048, B=64] float32
//   Y[j,e,b] = ((2*x[b,j]+1) >> min(E-1-e, 31)) & 1
// v = 2*x+1 <= 4095 < 2^12  =>  bit is 0 for all e < E-13 = 2035.
// Only the last 13 e-columns per j are nonzero (~0.64% of 1.07 GB).
//
// Session history (all measured on sm_103a):
//   R3  flat 2x/thr (split halves):     145.8us, DRAM 89.3%
//   R4  flat 4x/thr (split quarters):   145.5us, DRAM 89.2%  <- BEST
//   R7  persistent 1-wave grid-stride:  174.1us, DRAM 75.0%  (worse:
//       loop-carried serialization starves the store pipe)
//   R9  R4 confirm:                     145.6us, DRAM 89.5%
//   R10 128-thread blocks:              145.5us, DRAM 89.1%  (neutral)
//   R11 per-thread-contiguous 4x:       244.2us, DRAM 52.9%, L1 88.3%
//       (worse: lanes 64B apart -> 16 lines/warp-store instead of 4;
//        L1tex wavefront-bound. Lane-contiguity is what matters.)
// Frozen at the HBM3e write roofline: ~7.07 TB/s (88.5% of 8TB/s
// spec). The ~11% DRAM idle is intrinsic write-stream behavior.

constexpr int E_DIM = 2048;
constexpr unsigned NONZERO_E_START = E_DIM - 13;  // 2035

// Total float4 elements: J * E * B / 4 = 2048 * 2048 * 16 = 67,108,864
constexpr unsigned TOTAL_F4 = (unsigned)E_DIM * (unsigned)E_DIM * 16u;
constexpr unsigned QUARTER_F4 = TOTAL_F4 / 4;     // 16,777,216

__device__ __forceinline__ float4 compute_f4(const int* __restrict__ x,
                                             unsigned idx4) {
    // Each (j,e) pair owns B=64 consecutive floats = 16 float4s.
    unsigned pair = idx4 >> 4;            // j * E + e
    unsigned e    = pair & (E_DIM - 1);   // E is a power of two

    float4 val = make_float4(0.f, 0.f, 0.f, 0.f);
    if (e >= NONZERO_E_START) {
        unsigned j = pair >> 11;          // pair / E
        unsigned b = (idx4 & 15u) << 2;   // first of 4 batch lanes
        int shift = (E_DIM - 1) - (int)e; // in [0, 12]
        // x layout: [B, E] row-major -> x[b*E + j]
        int v0 = 2 * __ldg(&x[(b + 0) * E_DIM + j]) + 1;
        int v1 = 2 * __ldg(&x[(b + 1) * E_DIM + j]) + 1;
        int v2 = 2 * __ldg(&x[(b + 2) * E_DIM + j]) + 1;
        int v3 = 2 * __ldg(&x[(b + 3) * E_DIM + j]) + 1;
        val.x = (float)((v0 >> shift) & 1);
        val.y = (float)((v1 >> shift) & 1);
        val.z = (float)((v2 >> shift) & 1);
        val.w = (float)((v3 >> shift) & 1);
    }
    return val;
}

// Streaming store: evict-first, output is dead-on-write (no reuse).
__device__ __forceinline__ void stg_cs_f4(float4* p, float4 v) {
    asm volatile("st.global.cs.v4.f32 [%0], {%1, %2, %3, %4};"
                 :: "l"(p), "f"(v.x), "f"(v.y), "f"(v.z), "f"(v.w)
                 : "memory");
}

__global__ void embedding_bits_kernel(const int* __restrict__ x,
                                      float4* __restrict__ out) {
    unsigned idx4 = blockIdx.x * blockDim.x + threadIdx.x;  // < QUARTER_F4
    // Four independent STG.128.CS per thread. Consecutive lanes hit
    // consecutive 16B -> each warp store is one 512B burst (4 lines).
    float4 a = compute_f4(x, idx4);
    float4 b = compute_f4(x, idx4 + QUARTER_F4);
    float4 c = compute_f4(x, idx4 + 2 * QUARTER_F4);
    float4 d = compute_f4(x, idx4 + 3 * QUARTER_F4);
    stg_cs_f4(&out[idx4], a);
    stg_cs_f4(&out[idx4 + QUARTER_F4], b);
    stg_cs_f4(&out[idx4 + 2 * QUARTER_F4], c);
    stg_cs_f4(&out[idx4 + 3 * QUARTER_F4], d);
}

extern "C" void kernel_launch(void* const* d_in, const int* in_sizes, int n_in,
                              void* d_out, int out_size) {
    const int* x = (const int*)d_in[0];
    float4* out = (float4*)d_out;

    constexpr int THREADS = 256;
    constexpr unsigned BLOCKS = QUARTER_F4 / THREADS;  // 65,536 (exact)
    embedding_bits_kernel<<<BLOCKS, THREADS>>>(x, out);
}